// round 12
// baseline (speedup 1.0000x reference)
#include <cuda_runtime.h>

#define MAXB 256
#define MAXC 1024

typedef unsigned long long ull;
typedef unsigned int uint;

// Scratch (static device globals — no allocation allowed)
__device__ __align__(16) float g_W[MAXB * MAXC];  // w[i,c] = m_counts^2
__device__ int   g_modmax_i[MAXB];   // int-encoded non-negative float, atomicMax
__device__ int   g_idmin_i[MAXB];    // int-encoded non-negative float, atomicMin

// ---- packed f32x2 helpers (Blackwell sm_103a) ----
__device__ __forceinline__ ull f2_add(ull a, ull b) {
    ull r; asm("add.rn.f32x2 %0, %1, %2;" : "=l"(r) : "l"(a), "l"(b)); return r;
}
__device__ __forceinline__ ull f2_mul(ull a, ull b) {
    ull r; asm("mul.rn.f32x2 %0, %1, %2;" : "=l"(r) : "l"(a), "l"(b)); return r;
}
__device__ __forceinline__ ull f2_fma(ull a, ull b, ull c) {
    ull r; asm("fma.rn.f32x2 %0, %1, %2, %3;" : "=l"(r) : "l"(a), "l"(b), "l"(c)); return r;
}
__device__ __forceinline__ float f2_hsum(ull v) {
    return __uint_as_float((uint)v) + __uint_as_float((uint)(v >> 32));
}

__device__ __forceinline__ float warpReduceSum(float v) {
#pragma unroll
    for (int o = 16; o > 0; o >>= 1)
        v += __shfl_xor_sync(0xffffffffu, v, o);
    return v;
}

__device__ __forceinline__ float blockReduceSum(float v, float* sbuf) {
    const int tid = threadIdx.x;
    v = warpReduceSum(v);
    if ((tid & 31) == 0) sbuf[tid >> 5] = v;
    __syncthreads();
    float r = 0.f;
    if (tid == 0) {
        const int nw = (blockDim.x + 31) >> 5;
        for (int w = 0; w < nw; ++w) r += sbuf[w];
    }
    __syncthreads();
    return r;
}

// ---------------------------------------------------------------------------
// Phase 1 (fast path, C == 1024): ONE block of 1024 threads per row i.
// ---------------------------------------------------------------------------
__global__ __launch_bounds__(1024) void p1_big(
    const float* __restrict__ x,
    const int* __restrict__ targets,
    const int* __restrict__ subs,
    const int* __restrict__ mcp,
    int B) {
    const int i = blockIdx.x;
    const int tid = threadIdx.x;
    const int lane = tid & 31;
    const int warp = tid >> 5;
    const int C = 1024;

    __shared__ unsigned s_match[8];
    __shared__ unsigned s_valid[8];
    __shared__ int s_nb[16];
    __shared__ float s_thr[16];
    __shared__ int s_mc;

    if (tid == 0) {
        g_modmax_i[i] = 0;             // max over non-negative floats
        g_idmin_i[i] = 0x7f800000;     // +inf
    }

    const int ti = __ldg(&targets[i]);
    const int si = __ldg(&subs[i]);
    if (warp < 8) {
        const int j = tid;             // warp w covers group w (j = w*32+lane)
        const bool valid = (j < B);
        const int tj = valid ? __ldg(&targets[j]) : -1;
        const int sj = valid ? __ldg(&subs[j]) : -1;
        const unsigned mm = __ballot_sync(0xffffffffu, valid && tj == ti && sj == si);
        const unsigned vv = __ballot_sync(0xffffffffu, valid);
        if (lane == 0) { s_match[warp] = mm; s_valid[warp] = vv; }
    }
    __syncthreads();

    if (tid == 0) {
        int mc = __ldg(mcp);
        if (mc > 16) mc = 16;
        if (mc < 0) mc = 0;
        int cnt = 0;
        for (int w = 0; w < 8 && cnt < mc; ++w) {
            unsigned m = s_match[w];
            while (m && cnt < mc) { s_nb[cnt++] = w * 32 + (__ffs(m) - 1); m &= m - 1; }
        }
        for (int w = 0; w < 8 && cnt < mc; ++w) {
            unsigned m = s_valid[w] & ~s_match[w];
            while (m && cnt < mc) { s_nb[cnt++] = w * 32 + (__ffs(m) - 1); m &= m - 1; }
        }
        s_mc = cnt;
    }
    __syncthreads();

    const int mc = s_mc;
    const int c = tid;
    const bool fast = (mc <= 8);

    // Early W-loop loads (overlap with threshold loads below)
    const float xic = __ldg(&x[(size_t)i * C + c]);
    float xnb[8];
    if (fast) {
#pragma unroll
        for (int k = 0; k < 8; ++k)
            xnb[k] = (k < mc) ? __ldg(&x[(size_t)s_nb[k] * C + c]) : 0.f;
    }

    const float4* __restrict__ xi4 = reinterpret_cast<const float4*>(x + (size_t)i * C);
    if (warp < mc) {
        const int k = warp;
        const float4* __restrict__ xn4 =
            reinterpret_cast<const float4*>(x + (size_t)s_nb[k] * C);
        float s = 0.f;
#pragma unroll
        for (int q = 0; q < 8; ++q) {
            const float4 a = __ldg(&xi4[lane + 32 * q]);
            const float4 b = __ldg(&xn4[lane + 32 * q]);
            s += fabsf(a.x - b.x) + fabsf(a.y - b.y) +
                 fabsf(a.z - b.z) + fabsf(a.w - b.w);
        }
        s = warpReduceSum(s);
        if (lane == 0) s_thr[k] = (s / (float)C) * 0.5f;
    }
    __syncthreads();

    int cnt = 0;
    if (fast) {
#pragma unroll
        for (int k = 0; k < 8; ++k)
            if (k < mc)
                cnt += (fabsf(xic - xnb[k]) < s_thr[k]) ? 1 : 0;
    } else {
        for (int k = 0; k < mc; ++k)
            cnt += (fabsf(xic - __ldg(&x[(size_t)s_nb[k] * C + c])) < s_thr[k]) ? 1 : 0;
    }
    g_W[(size_t)i * C + c] = (float)(cnt * cnt);
}

// ---------------------------------------------------------------------------
// Phase 2 fast path (C == 1024, B % 32 == 0): symmetric upper-triangle tiles,
// packed f32x2 v3: no ad[] array (xj reloaded from L1 in pass 2, |d|
// recomputed) -> ~70 regs -> 3 blocks/SM (85-reg clamp, no spills).
// grid (nt*(nt+1)/2, 16): blockIdx.y = rowgroup*4 + jquarter; 8 j per block.
// ---------------------------------------------------------------------------
__global__ __launch_bounds__(256, 3) void phase2_sym(
    const float* __restrict__ x,
    const int* __restrict__ targets,
    int B) {
    const int lane = threadIdx.x & 31;
    const int warp = threadIdx.x >> 5;
    const int nt = B >> 5;

    __shared__ ulonglong2 s_wi[8][256];   // 32 KB: packed W row per warp

    // map blockIdx.x -> (tu, tv), tu <= tv, row-major upper triangle
    int t = blockIdx.x;
    int tu = 0;
    while (t >= nt - tu) { t -= (nt - tu); ++tu; }
    const int tv = tu + t;

    const int rowgroup = blockIdx.y >> 2;   // 0..3
    const int jq = blockIdx.y & 3;          // 0..3
    const int i = tu * 32 + rowgroup * 8 + warp;
    const int jbase = tv * 32 + jq * 8;
    const bool crossTile = (tu != tv);

    const ull SIGN2 = 0x8000000080000000ULL;
    const ull ABS2  = 0x7fffffff7fffffffULL;

    const int ti = __ldg(&targets[i]);
    // row stride: 1024 floats = 256 × 16B
    const ulonglong2* __restrict__ xrow =
        reinterpret_cast<const ulonglong2*>(x) + (size_t)i * 256;
    const ulonglong2* __restrict__ wrow =
        reinterpret_cast<const ulonglong2*>(g_W) + (size_t)i * 256;

    ull xin[16];   // packed (-xi) pairs
#pragma unroll
    for (int k = 0; k < 8; ++k) {
        const ulonglong2 v = __ldg(&xrow[lane + 32 * k]);
        xin[2 * k]     = v.x ^ SIGN2;
        xin[2 * k + 1] = v.y ^ SIGN2;
        s_wi[warp][lane + 32 * k] = __ldg(&wrow[lane + 32 * k]);
    }
    __syncwarp();  // s_wi[warp] used only by this warp

    float modmax = 0.f;
    float idmin = __int_as_float(0x7f800000);

#pragma unroll 1
    for (int jj = 0; jj < 8; ++jj) {
        const int j = jbase + jj;
        const ulonglong2* __restrict__ xj2 =
            reinterpret_cast<const ulonglong2*>(x) + (size_t)j * 256;

        // pass 1 (packed): accumulate sum |xj - xi| (no ad storage)
        ull sa = 0, sb = 0;
#pragma unroll
        for (int k = 0; k < 8; ++k) {
            const ulonglong2 v = __ldg(&xj2[lane + 32 * k]);
            sa = f2_add(sa, f2_add(xin[2 * k],     v.x) & ABS2);
            sb = f2_add(sb, f2_add(xin[2 * k + 1], v.y) & ABS2);
        }
        float sabs = f2_hsum(f2_add(sa, sb));
        sabs = warpReduceSum(sabs);
        const float thr = sabs * (0.5f / 1024.f);
        const uint thrBits = __float_as_uint(thr);   // thr >= 0

        // pass 2: reload xj (L1-hot), recompute |d|, masked idsum + modsum
        const ulonglong2* __restrict__ wj2 =
            reinterpret_cast<const ulonglong2*>(g_W) + (size_t)j * 256;
        ull mod2 = 0;
        float idsum = 0.f;
#pragma unroll
        for (int k = 0; k < 8; ++k) {
            const ulonglong2 v = __ldg(&xj2[lane + 32 * k]);
            const ulonglong2 wv = __ldg(&wj2[lane + 32 * k]);
            const ulonglong2 wiv = s_wi[warp][lane + 32 * k];
            {
                const ull a = f2_add(xin[2 * k], v.x) & ABS2;
                const ull d2 = f2_mul(a, a);
                mod2 = f2_fma(d2, f2_mul(wiv.x, wv.x), mod2);
                if ((uint)a < thrBits)         idsum += __uint_as_float((uint)d2);
                if ((uint)(a >> 32) < thrBits) idsum += __uint_as_float((uint)(d2 >> 32));
            }
            {
                const ull a = f2_add(xin[2 * k + 1], v.y) & ABS2;
                const ull d2 = f2_mul(a, a);
                mod2 = f2_fma(d2, f2_mul(wiv.y, wv.y), mod2);
                if ((uint)a < thrBits)         idsum += __uint_as_float((uint)d2);
                if ((uint)(a >> 32) < thrBits) idsum += __uint_as_float((uint)(d2 >> 32));
            }
        }
        float modsum = f2_hsum(mod2);
        idsum = warpReduceSum(idsum);
        modsum = warpReduceSum(modsum);

        const float modd = sqrtf(fmaxf(modsum, 1e-12f));
        const float idd = sqrtf(fmaxf(idsum, 1e-12f));
        const int tj = __ldg(&targets[j]);
        const bool diffT = (tj != ti);

        modmax = fmaxf(modmax, modd);
        if (diffT) idmin = fminf(idmin, idd);

        if (lane == 0 && crossTile) {
            atomicMax(&g_modmax_i[j], __float_as_int(modd));
            if (diffT) atomicMin(&g_idmin_i[j], __float_as_int(idd));
        }
    }

    if (lane == 0) {
        atomicMax(&g_modmax_i[i], __float_as_int(modmax));
        atomicMin(&g_idmin_i[i], __float_as_int(idmin));
    }
}

// ---------------------------------------------------------------------------
// Finalize: hinge + mean.
// ---------------------------------------------------------------------------
__global__ void finalize_kernel(float* __restrict__ out, int B) {
    const int tid = threadIdx.x;
    __shared__ float s_red[8];
    float pr = 0.f;
    for (int i = tid; i < B; i += blockDim.x) {
        const float mm = __int_as_float(g_modmax_i[i]);
        const float im = __int_as_float(g_idmin_i[i]);
        pr += fmaxf(mm * 10.f - im, 0.f);   // im=+inf -> -inf -> 0
    }
    pr = blockReduceSum(pr, s_red);
    if (tid == 0) out[0] = pr / (float)B;
}

// ---------------------------------------------------------------------------
// Generic fallback path (any C/B).
// ---------------------------------------------------------------------------
__global__ __launch_bounds__(256) void phase1_kernel(
    const float* __restrict__ x,
    const int* __restrict__ targets,
    const int* __restrict__ subs,
    const int* __restrict__ mcp,
    int B, int C) {
    const int i = blockIdx.x;
    const int tid = threadIdx.x;
    const int lane = tid & 31;
    const int warp = tid >> 5;

    __shared__ int s_t[MAXB];
    __shared__ int s_s[MAXB];
    __shared__ unsigned s_match[8];
    __shared__ unsigned s_valid[8];
    __shared__ int s_nb[16];
    __shared__ float s_thr[16];
    __shared__ int s_mc;

    for (int j = tid; j < B; j += blockDim.x) {
        s_t[j] = targets[j];
        s_s[j] = subs[j];
    }
    if (tid == 0) {
        g_modmax_i[i] = 0;
        g_idmin_i[i] = 0x7f800000;
    }
    __syncthreads();

    {
        const int ti = s_t[i], si = s_s[i];
        const int j = tid;
        const bool valid = (j < B);
        const bool match = valid && (s_t[j] == ti) && (s_s[j] == si);
        const unsigned mm = __ballot_sync(0xffffffffu, match);
        const unsigned vv = __ballot_sync(0xffffffffu, valid);
        if (lane == 0) { s_match[warp] = mm; s_valid[warp] = vv; }
    }
    __syncthreads();

    if (tid == 0) {
        int mc = mcp[0];
        if (mc > 16) mc = 16;
        if (mc < 0) mc = 0;
        int cnt = 0;
        for (int w = 0; w < 8 && cnt < mc; ++w) {
            unsigned m = s_match[w];
            while (m && cnt < mc) { s_nb[cnt++] = w * 32 + (__ffs(m) - 1); m &= m - 1; }
        }
        for (int w = 0; w < 8 && cnt < mc; ++w) {
            unsigned m = s_valid[w] & ~s_match[w];
            while (m && cnt < mc) { s_nb[cnt++] = w * 32 + (__ffs(m) - 1); m &= m - 1; }
        }
        s_mc = cnt;
    }
    __syncthreads();

    const int mc = s_mc;
    const float* __restrict__ xi = x + (size_t)i * C;

    for (int k = warp; k < mc; k += (blockDim.x >> 5)) {
        const float* __restrict__ xn = x + (size_t)s_nb[k] * C;
        float s = 0.f;
        for (int c = lane; c < C; c += 32)
            s += fabsf(xi[c] - xn[c]);
        s = warpReduceSum(s);
        if (lane == 0) s_thr[k] = (s / (float)C) * 0.5f;
    }
    __syncthreads();

    for (int c = tid; c < C; c += blockDim.x) {
        const float xic = xi[c];
        int cnt = 0;
        for (int k = 0; k < mc; ++k)
            cnt += (fabsf(xic - x[(size_t)s_nb[k] * C + c]) < s_thr[k]) ? 1 : 0;
        g_W[(size_t)i * C + c] = (float)(cnt * cnt);
    }
}

__global__ void phase2_generic(const float* __restrict__ x,
                               const int* __restrict__ targets,
                               int B, int C, int jtile) {
    const int i = blockIdx.y;
    const int jt = blockIdx.x;
    const int tid = threadIdx.x;
    __shared__ float s_red[8];
    __shared__ float s_thr;

    const float* xi = x + (size_t)i * C;
    const float* wi = g_W + (size_t)i * C;
    const int ti = targets[i];
    float modmax = 0.f;
    float idmin = __int_as_float(0x7f800000);

    const int j0 = jt * jtile;
    const int j1 = (j0 + jtile < B) ? (j0 + jtile) : B;

    for (int j = j0; j < j1; ++j) {
        const float* xj = x + (size_t)j * C;
        const float* wj = g_W + (size_t)j * C;
        float sabs = 0.f;
        for (int c = tid; c < C; c += blockDim.x)
            sabs += fabsf(xi[c] - xj[c]);
        sabs = blockReduceSum(sabs, s_red);
        if (tid == 0) s_thr = (sabs / (float)C) * 0.5f;
        __syncthreads();
        const float thr = s_thr;

        float idsum = 0.f, modsum = 0.f;
        for (int c = tid; c < C; c += blockDim.x) {
            const float dd = xi[c] - xj[c];
            const float d2 = dd * dd;
            if (fabsf(dd) < thr) idsum += d2;
            modsum += d2 * wi[c] * wj[c];
        }
        idsum = blockReduceSum(idsum, s_red);
        modsum = blockReduceSum(modsum, s_red);
        if (tid == 0) {
            const float modd = sqrtf(fmaxf(modsum, 1e-12f));
            modmax = fmaxf(modmax, modd);
            if (targets[j] != ti) {
                const float idd = sqrtf(fmaxf(idsum, 1e-12f));
                idmin = fminf(idmin, idd);
            }
        }
        __syncthreads();
    }
    if (tid == 0) {
        atomicMax(&g_modmax_i[i], __float_as_int(modmax));
        atomicMin(&g_idmin_i[i], __float_as_int(idmin));
    }
}

// ---------------------------------------------------------------------------
extern "C" void kernel_launch(void* const* d_in, const int* in_sizes, int n_in,
                              void* d_out, int out_size) {
    const float* x = (const float*)d_in[0];
    const int* targets = (const int*)d_in[1];
    const int* subs = (const int*)d_in[2];
    const int* mcp = (const int*)d_in[3];

    const int B = in_sizes[1];             // rows (256)
    const int C = in_sizes[0] / B;         // channels (1024)

    if (C == 1024 && (B & 31) == 0 && B >= 32 && B <= MAXB) {
        p1_big<<<B, 1024>>>(x, targets, subs, mcp, B);
        const int nt = B >> 5;
        dim3 grid(nt * (nt + 1) / 2, 16);
        phase2_sym<<<grid, 256>>>(x, targets, B);
        finalize_kernel<<<1, 256>>>((float*)d_out, B);
    } else {
        phase1_kernel<<<B, 256>>>(x, targets, subs, mcp, B, C);
        const int JT = 8;
        const int jtile = (B + JT - 1) / JT;
        dim3 grid(JT, B);
        phase2_generic<<<grid, 128>>>(x, targets, B, C, jtile);
        finalize_kernel<<<1, 256>>>((float*)d_out, B);
    }
}

// round 14
// speedup vs baseline: 1.2378x; 1.2378x over previous
#include <cuda_runtime.h>

#define MAXB 256
#define MAXC 1024

typedef unsigned long long ull;
typedef unsigned int uint;

// Scratch (static device globals — no allocation allowed)
__device__ __align__(16) float g_W[MAXB * MAXC];  // w[i,c] = m_counts^2
__device__ int   g_modmax_i[MAXB];   // int-encoded non-negative float, atomicMax
__device__ int   g_idmin_i[MAXB];    // int-encoded non-negative float, atomicMin

// ---- packed f32x2 helpers (Blackwell sm_103a) ----
__device__ __forceinline__ ull f2_add(ull a, ull b) {
    ull r; asm("add.rn.f32x2 %0, %1, %2;" : "=l"(r) : "l"(a), "l"(b)); return r;
}
__device__ __forceinline__ ull f2_mul(ull a, ull b) {
    ull r; asm("mul.rn.f32x2 %0, %1, %2;" : "=l"(r) : "l"(a), "l"(b)); return r;
}
__device__ __forceinline__ ull f2_fma(ull a, ull b, ull c) {
    ull r; asm("fma.rn.f32x2 %0, %1, %2, %3;" : "=l"(r) : "l"(a), "l"(b), "l"(c)); return r;
}
__device__ __forceinline__ float f2_hsum(ull v) {
    return __uint_as_float((uint)v) + __uint_as_float((uint)(v >> 32));
}

__device__ __forceinline__ float warpReduceSum(float v) {
#pragma unroll
    for (int o = 16; o > 0; o >>= 1)
        v += __shfl_xor_sync(0xffffffffu, v, o);
    return v;
}

__device__ __forceinline__ float blockReduceSum(float v, float* sbuf) {
    const int tid = threadIdx.x;
    v = warpReduceSum(v);
    if ((tid & 31) == 0) sbuf[tid >> 5] = v;
    __syncthreads();
    float r = 0.f;
    if (tid == 0) {
        const int nw = (blockDim.x + 31) >> 5;
        for (int w = 0; w < nw; ++w) r += sbuf[w];
    }
    __syncthreads();
    return r;
}

// ---------------------------------------------------------------------------
// Phase 1 (fast path, C == 1024): ONE block of 1024 threads per row i.
// ---------------------------------------------------------------------------
__global__ __launch_bounds__(1024) void p1_big(
    const float* __restrict__ x,
    const int* __restrict__ targets,
    const int* __restrict__ subs,
    const int* __restrict__ mcp,
    int B) {
    const int i = blockIdx.x;
    const int tid = threadIdx.x;
    const int lane = tid & 31;
    const int warp = tid >> 5;
    const int C = 1024;

    __shared__ unsigned s_match[8];
    __shared__ unsigned s_valid[8];
    __shared__ int s_nb[16];
    __shared__ float s_thr[16];
    __shared__ int s_mc;

    if (tid == 0) {
        g_modmax_i[i] = 0;             // max over non-negative floats
        g_idmin_i[i] = 0x7f800000;     // +inf
    }

    const int ti = __ldg(&targets[i]);
    const int si = __ldg(&subs[i]);
    if (warp < 8) {
        const int j = tid;             // warp w covers group w (j = w*32+lane)
        const bool valid = (j < B);
        const int tj = valid ? __ldg(&targets[j]) : -1;
        const int sj = valid ? __ldg(&subs[j]) : -1;
        const unsigned mm = __ballot_sync(0xffffffffu, valid && tj == ti && sj == si);
        const unsigned vv = __ballot_sync(0xffffffffu, valid);
        if (lane == 0) { s_match[warp] = mm; s_valid[warp] = vv; }
    }
    __syncthreads();

    if (tid == 0) {
        int mc = __ldg(mcp);
        if (mc > 16) mc = 16;
        if (mc < 0) mc = 0;
        int cnt = 0;
        for (int w = 0; w < 8 && cnt < mc; ++w) {
            unsigned m = s_match[w];
            while (m && cnt < mc) { s_nb[cnt++] = w * 32 + (__ffs(m) - 1); m &= m - 1; }
        }
        for (int w = 0; w < 8 && cnt < mc; ++w) {
            unsigned m = s_valid[w] & ~s_match[w];
            while (m && cnt < mc) { s_nb[cnt++] = w * 32 + (__ffs(m) - 1); m &= m - 1; }
        }
        s_mc = cnt;
    }
    __syncthreads();

    const int mc = s_mc;
    const int c = tid;
    const bool fast = (mc <= 8);

    // Early W-loop loads (overlap with threshold loads below)
    const float xic = __ldg(&x[(size_t)i * C + c]);
    float xnb[8];
    if (fast) {
#pragma unroll
        for (int k = 0; k < 8; ++k)
            xnb[k] = (k < mc) ? __ldg(&x[(size_t)s_nb[k] * C + c]) : 0.f;
    }

    const float4* __restrict__ xi4 = reinterpret_cast<const float4*>(x + (size_t)i * C);
    if (warp < mc) {
        const int k = warp;
        const float4* __restrict__ xn4 =
            reinterpret_cast<const float4*>(x + (size_t)s_nb[k] * C);
        float s = 0.f;
#pragma unroll
        for (int q = 0; q < 8; ++q) {
            const float4 a = __ldg(&xi4[lane + 32 * q]);
            const float4 b = __ldg(&xn4[lane + 32 * q]);
            s += fabsf(a.x - b.x) + fabsf(a.y - b.y) +
                 fabsf(a.z - b.z) + fabsf(a.w - b.w);
        }
        s = warpReduceSum(s);
        if (lane == 0) s_thr[k] = (s / (float)C) * 0.5f;
    }
    __syncthreads();

    int cnt = 0;
    if (fast) {
#pragma unroll
        for (int k = 0; k < 8; ++k)
            if (k < mc)
                cnt += (fabsf(xic - xnb[k]) < s_thr[k]) ? 1 : 0;
    } else {
        for (int k = 0; k < mc; ++k)
            cnt += (fabsf(xic - __ldg(&x[(size_t)s_nb[k] * C + c])) < s_thr[k]) ? 1 : 0;
    }
    g_W[(size_t)i * C + c] = (float)(cnt * cnt);
}

// ---------------------------------------------------------------------------
// Phase 2 fast path (C == 1024, B % 32 == 0): symmetric upper-triangle tiles,
// packed f32x2 (round-11 form: ad[16] stored, no launch-bounds clamp).
// wj[0..3] prefetched BEFORE the sabs shfl chain so their memory latency
// hides under the reduction. grid (nt*(nt+1)/2, 8); block 256 (8 warps).
// ---------------------------------------------------------------------------
__global__ __launch_bounds__(256) void phase2_sym(
    const float* __restrict__ x,
    const int* __restrict__ targets,
    int B) {
    const int lane = threadIdx.x & 31;
    const int warp = threadIdx.x >> 5;
    const int nt = B >> 5;

    __shared__ ulonglong2 s_wi[8][256];   // 32 KB: packed W row per warp

    // map blockIdx.x -> (tu, tv), tu <= tv, row-major upper triangle
    int t = blockIdx.x;
    int tu = 0;
    while (t >= nt - tu) { t -= (nt - tu); ++tu; }
    const int tv = tu + t;

    const int rowgroup = blockIdx.y >> 1;
    const int jhalf = blockIdx.y & 1;
    const int i = tu * 32 + rowgroup * 8 + warp;
    const int jbase = tv * 32 + jhalf * 16;
    const bool crossTile = (tu != tv);

    const ull SIGN2 = 0x8000000080000000ULL;
    const ull ABS2  = 0x7fffffff7fffffffULL;

    const int ti = __ldg(&targets[i]);
    // row stride: 1024 floats = 256 × 16B
    const ulonglong2* __restrict__ xrow =
        reinterpret_cast<const ulonglong2*>(x) + (size_t)i * 256;
    const ulonglong2* __restrict__ wrow =
        reinterpret_cast<const ulonglong2*>(g_W) + (size_t)i * 256;

    ull xin[16];   // packed (-xi) pairs
#pragma unroll
    for (int k = 0; k < 8; ++k) {
        const ulonglong2 v = __ldg(&xrow[lane + 32 * k]);
        xin[2 * k]     = v.x ^ SIGN2;
        xin[2 * k + 1] = v.y ^ SIGN2;
        s_wi[warp][lane + 32 * k] = __ldg(&wrow[lane + 32 * k]);
    }
    __syncwarp();  // s_wi[warp] used only by this warp

    float modmax = 0.f;
    float idmin = __int_as_float(0x7f800000);

#pragma unroll 1
    for (int jj = 0; jj < 16; ++jj) {
        const int j = jbase + jj;
        const ulonglong2* __restrict__ xj2 =
            reinterpret_cast<const ulonglong2*>(x) + (size_t)j * 256;
        const ulonglong2* __restrict__ wj2 =
            reinterpret_cast<const ulonglong2*>(g_W) + (size_t)j * 256;

        // pass 1 (packed): ad = |xj - xi|, accumulate sum of |.|
        ull ad[16];
        ull sa = 0, sb = 0;
#pragma unroll
        for (int k = 0; k < 8; ++k) {
            const ulonglong2 v = __ldg(&xj2[lane + 32 * k]);
            const ull a = f2_add(xin[2 * k],     v.x) & ABS2;
            const ull b = f2_add(xin[2 * k + 1], v.y) & ABS2;
            ad[2 * k] = a;
            ad[2 * k + 1] = b;
            sa = f2_add(sa, a);
            sb = f2_add(sb, b);
        }

        // prefetch wj[0..3] — these loads don't depend on thr, so their
        // latency overlaps the shfl reduction chain below
        ulonglong2 wjp[4];
#pragma unroll
        for (int k = 0; k < 4; ++k)
            wjp[k] = __ldg(&wj2[lane + 32 * k]);

        float sabs = f2_hsum(f2_add(sa, sb));
        sabs = warpReduceSum(sabs);
        const float thr = sabs * (0.5f / 1024.f);
        const uint thrBits = __float_as_uint(thr);   // thr >= 0

        // pass 2 (packed): modsum packed fma; idsum scalar pred-FADD on halves
        ull mod2 = 0;
        float idsum = 0.f;
#pragma unroll
        for (int k = 0; k < 8; ++k) {
            const ulonglong2 wv = (k < 4) ? wjp[k] : __ldg(&wj2[lane + 32 * k]);
            const ulonglong2 wiv = s_wi[warp][lane + 32 * k];
            {
                const ull a = ad[2 * k];
                const ull d2 = f2_mul(a, a);
                mod2 = f2_fma(d2, f2_mul(wiv.x, wv.x), mod2);
                if ((uint)a < thrBits)         idsum += __uint_as_float((uint)d2);
                if ((uint)(a >> 32) < thrBits) idsum += __uint_as_float((uint)(d2 >> 32));
            }
            {
                const ull a = ad[2 * k + 1];
                const ull d2 = f2_mul(a, a);
                mod2 = f2_fma(d2, f2_mul(wiv.y, wv.y), mod2);
                if ((uint)a < thrBits)         idsum += __uint_as_float((uint)d2);
                if ((uint)(a >> 32) < thrBits) idsum += __uint_as_float((uint)(d2 >> 32));
            }
        }
        float modsum = f2_hsum(mod2);
        idsum = warpReduceSum(idsum);
        modsum = warpReduceSum(modsum);

        const float modd = sqrtf(fmaxf(modsum, 1e-12f));
        const float idd = sqrtf(fmaxf(idsum, 1e-12f));
        const int tj = __ldg(&targets[j]);
        const bool diffT = (tj != ti);

        modmax = fmaxf(modmax, modd);
        if (diffT) idmin = fminf(idmin, idd);

        if (lane == 0 && crossTile) {
            atomicMax(&g_modmax_i[j], __float_as_int(modd));
            if (diffT) atomicMin(&g_idmin_i[j], __float_as_int(idd));
        }
    }

    if (lane == 0) {
        atomicMax(&g_modmax_i[i], __float_as_int(modmax));
        atomicMin(&g_idmin_i[i], __float_as_int(idmin));
    }
}

// ---------------------------------------------------------------------------
// Finalize: hinge + mean.
// ---------------------------------------------------------------------------
__global__ void finalize_kernel(float* __restrict__ out, int B) {
    const int tid = threadIdx.x;
    __shared__ float s_red[8];
    float pr = 0.f;
    for (int i = tid; i < B; i += blockDim.x) {
        const float mm = __int_as_float(g_modmax_i[i]);
        const float im = __int_as_float(g_idmin_i[i]);
        pr += fmaxf(mm * 10.f - im, 0.f);   // im=+inf -> -inf -> 0
    }
    pr = blockReduceSum(pr, s_red);
    if (tid == 0) out[0] = pr / (float)B;
}

// ---------------------------------------------------------------------------
// Generic fallback path (any C/B).
// ---------------------------------------------------------------------------
__global__ __launch_bounds__(256) void phase1_kernel(
    const float* __restrict__ x,
    const int* __restrict__ targets,
    const int* __restrict__ subs,
    const int* __restrict__ mcp,
    int B, int C) {
    const int i = blockIdx.x;
    const int tid = threadIdx.x;
    const int lane = tid & 31;
    const int warp = tid >> 5;

    __shared__ int s_t[MAXB];
    __shared__ int s_s[MAXB];
    __shared__ unsigned s_match[8];
    __shared__ unsigned s_valid[8];
    __shared__ int s_nb[16];
    __shared__ float s_thr[16];
    __shared__ int s_mc;

    for (int j = tid; j < B; j += blockDim.x) {
        s_t[j] = targets[j];
        s_s[j] = subs[j];
    }
    if (tid == 0) {
        g_modmax_i[i] = 0;
        g_idmin_i[i] = 0x7f800000;
    }
    __syncthreads();

    {
        const int ti = s_t[i], si = s_s[i];
        const int j = tid;
        const bool valid = (j < B);
        const bool match = valid && (s_t[j] == ti) && (s_s[j] == si);
        const unsigned mm = __ballot_sync(0xffffffffu, match);
        const unsigned vv = __ballot_sync(0xffffffffu, valid);
        if (lane == 0) { s_match[warp] = mm; s_valid[warp] = vv; }
    }
    __syncthreads();

    if (tid == 0) {
        int mc = mcp[0];
        if (mc > 16) mc = 16;
        if (mc < 0) mc = 0;
        int cnt = 0;
        for (int w = 0; w < 8 && cnt < mc; ++w) {
            unsigned m = s_match[w];
            while (m && cnt < mc) { s_nb[cnt++] = w * 32 + (__ffs(m) - 1); m &= m - 1; }
        }
        for (int w = 0; w < 8 && cnt < mc; ++w) {
            unsigned m = s_valid[w] & ~s_match[w];
            while (m && cnt < mc) { s_nb[cnt++] = w * 32 + (__ffs(m) - 1); m &= m - 1; }
        }
        s_mc = cnt;
    }
    __syncthreads();

    const int mc = s_mc;
    const float* __restrict__ xi = x + (size_t)i * C;

    for (int k = warp; k < mc; k += (blockDim.x >> 5)) {
        const float* __restrict__ xn = x + (size_t)s_nb[k] * C;
        float s = 0.f;
        for (int c = lane; c < C; c += 32)
            s += fabsf(xi[c] - xn[c]);
        s = warpReduceSum(s);
        if (lane == 0) s_thr[k] = (s / (float)C) * 0.5f;
    }
    __syncthreads();

    for (int c = tid; c < C; c += blockDim.x) {
        const float xic = xi[c];
        int cnt = 0;
        for (int k = 0; k < mc; ++k)
            cnt += (fabsf(xic - x[(size_t)s_nb[k] * C + c]) < s_thr[k]) ? 1 : 0;
        g_W[(size_t)i * C + c] = (float)(cnt * cnt);
    }
}

__global__ void phase2_generic(const float* __restrict__ x,
                               const int* __restrict__ targets,
                               int B, int C, int jtile) {
    const int i = blockIdx.y;
    const int jt = blockIdx.x;
    const int tid = threadIdx.x;
    __shared__ float s_red[8];
    __shared__ float s_thr;

    const float* xi = x + (size_t)i * C;
    const float* wi = g_W + (size_t)i * C;
    const int ti = targets[i];
    float modmax = 0.f;
    float idmin = __int_as_float(0x7f800000);

    const int j0 = jt * jtile;
    const int j1 = (j0 + jtile < B) ? (j0 + jtile) : B;

    for (int j = j0; j < j1; ++j) {
        const float* xj = x + (size_t)j * C;
        const float* wj = g_W + (size_t)j * C;
        float sabs = 0.f;
        for (int c = tid; c < C; c += blockDim.x)
            sabs += fabsf(xi[c] - xj[c]);
        sabs = blockReduceSum(sabs, s_red);
        if (tid == 0) s_thr = (sabs / (float)C) * 0.5f;
        __syncthreads();
        const float thr = s_thr;

        float idsum = 0.f, modsum = 0.f;
        for (int c = tid; c < C; c += blockDim.x) {
            const float dd = xi[c] - xj[c];
            const float d2 = dd * dd;
            if (fabsf(dd) < thr) idsum += d2;
            modsum += d2 * wi[c] * wj[c];
        }
        idsum = blockReduceSum(idsum, s_red);
        modsum = blockReduceSum(modsum, s_red);
        if (tid == 0) {
            const float modd = sqrtf(fmaxf(modsum, 1e-12f));
            modmax = fmaxf(modmax, modd);
            if (targets[j] != ti) {
                const float idd = sqrtf(fmaxf(idsum, 1e-12f));
                idmin = fminf(idmin, idd);
            }
        }
        __syncthreads();
    }
    if (tid == 0) {
        atomicMax(&g_modmax_i[i], __float_as_int(modmax));
        atomicMin(&g_idmin_i[i], __float_as_int(idmin));
    }
}

// ---------------------------------------------------------------------------
extern "C" void kernel_launch(void* const* d_in, const int* in_sizes, int n_in,
                              void* d_out, int out_size) {
    const float* x = (const float*)d_in[0];
    const int* targets = (const int*)d_in[1];
    const int* subs = (const int*)d_in[2];
    const int* mcp = (const int*)d_in[3];

    const int B = in_sizes[1];             // rows (256)
    const int C = in_sizes[0] / B;         // channels (1024)

    if (C == 1024 && (B & 31) == 0 && B >= 32 && B <= MAXB) {
        p1_big<<<B, 1024>>>(x, targets, subs, mcp, B);
        const int nt = B >> 5;
        dim3 grid(nt * (nt + 1) / 2, 8);
        phase2_sym<<<grid, 256>>>(x, targets, B);
        finalize_kernel<<<1, 256>>>((float*)d_out, B);
    } else {
        phase1_kernel<<<B, 256>>>(x, targets, subs, mcp, B, C);
        const int JT = 8;
        const int jtile = (B + JT - 1) / JT;
        dim3 grid(JT, B);
        phase2_generic<<<grid, 128>>>(x, targets, B, C, jtile);
        finalize_kernel<<<1, 256>>>((float*)d_out, B);
    }
}

// round 15
// speedup vs baseline: 1.2450x; 1.0058x over previous
#include <cuda_runtime.h>

#define MAXB 256
#define MAXC 1024

typedef unsigned long long ull;
typedef unsigned int uint;

// Scratch (static device globals — no allocation allowed)
__device__ __align__(16) float g_W[MAXB * MAXC];  // w[i,c] = m_counts^2
__device__ int   g_modmax_i[MAXB];   // int-encoded non-negative float, atomicMax
__device__ int   g_idmin_i[MAXB];    // int-encoded non-negative float, atomicMin

// ---- packed f32x2 helpers (Blackwell sm_103a) ----
__device__ __forceinline__ ull f2_add(ull a, ull b) {
    ull r; asm("add.rn.f32x2 %0, %1, %2;" : "=l"(r) : "l"(a), "l"(b)); return r;
}
__device__ __forceinline__ ull f2_mul(ull a, ull b) {
    ull r; asm("mul.rn.f32x2 %0, %1, %2;" : "=l"(r) : "l"(a), "l"(b)); return r;
}
__device__ __forceinline__ ull f2_fma(ull a, ull b, ull c) {
    ull r; asm("fma.rn.f32x2 %0, %1, %2, %3;" : "=l"(r) : "l"(a), "l"(b), "l"(c)); return r;
}
__device__ __forceinline__ float f2_hsum(ull v) {
    return __uint_as_float((uint)v) + __uint_as_float((uint)(v >> 32));
}

__device__ __forceinline__ float warpReduceSum(float v) {
#pragma unroll
    for (int o = 16; o > 0; o >>= 1)
        v += __shfl_xor_sync(0xffffffffu, v, o);
    return v;
}

__device__ __forceinline__ float blockReduceSum(float v, float* sbuf) {
    const int tid = threadIdx.x;
    v = warpReduceSum(v);
    if ((tid & 31) == 0) sbuf[tid >> 5] = v;
    __syncthreads();
    float r = 0.f;
    if (tid == 0) {
        const int nw = (blockDim.x + 31) >> 5;
        for (int w = 0; w < nw; ++w) r += sbuf[w];
    }
    __syncthreads();
    return r;
}

// ---------------------------------------------------------------------------
// Phase 1 (fast path, C == 1024): ONE block of 1024 threads per row i.
// ---------------------------------------------------------------------------
__global__ __launch_bounds__(1024) void p1_big(
    const float* __restrict__ x,
    const int* __restrict__ targets,
    const int* __restrict__ subs,
    const int* __restrict__ mcp,
    int B) {
    const int i = blockIdx.x;
    const int tid = threadIdx.x;
    const int lane = tid & 31;
    const int warp = tid >> 5;
    const int C = 1024;

    __shared__ unsigned s_match[8];
    __shared__ unsigned s_valid[8];
    __shared__ int s_nb[16];
    __shared__ float s_thr[16];
    __shared__ int s_mc;

    if (tid == 0) {
        g_modmax_i[i] = 0;             // max over non-negative floats
        g_idmin_i[i] = 0x7f800000;     // +inf
    }

    const int ti = __ldg(&targets[i]);
    const int si = __ldg(&subs[i]);
    if (warp < 8) {
        const int j = tid;             // warp w covers group w (j = w*32+lane)
        const bool valid = (j < B);
        const int tj = valid ? __ldg(&targets[j]) : -1;
        const int sj = valid ? __ldg(&subs[j]) : -1;
        const unsigned mm = __ballot_sync(0xffffffffu, valid && tj == ti && sj == si);
        const unsigned vv = __ballot_sync(0xffffffffu, valid);
        if (lane == 0) { s_match[warp] = mm; s_valid[warp] = vv; }
    }
    __syncthreads();

    if (tid == 0) {
        int mc = __ldg(mcp);
        if (mc > 16) mc = 16;
        if (mc < 0) mc = 0;
        int cnt = 0;
        for (int w = 0; w < 8 && cnt < mc; ++w) {
            unsigned m = s_match[w];
            while (m && cnt < mc) { s_nb[cnt++] = w * 32 + (__ffs(m) - 1); m &= m - 1; }
        }
        for (int w = 0; w < 8 && cnt < mc; ++w) {
            unsigned m = s_valid[w] & ~s_match[w];
            while (m && cnt < mc) { s_nb[cnt++] = w * 32 + (__ffs(m) - 1); m &= m - 1; }
        }
        s_mc = cnt;
    }
    __syncthreads();

    const int mc = s_mc;
    const int c = tid;
    const bool fast = (mc <= 8);

    // Early W-loop loads (overlap with threshold loads below)
    const float xic = __ldg(&x[(size_t)i * C + c]);
    float xnb[8];
    if (fast) {
#pragma unroll
        for (int k = 0; k < 8; ++k)
            xnb[k] = (k < mc) ? __ldg(&x[(size_t)s_nb[k] * C + c]) : 0.f;
    }

    const float4* __restrict__ xi4 = reinterpret_cast<const float4*>(x + (size_t)i * C);
    if (warp < mc) {
        const int k = warp;
        const float4* __restrict__ xn4 =
            reinterpret_cast<const float4*>(x + (size_t)s_nb[k] * C);
        float s = 0.f;
#pragma unroll
        for (int q = 0; q < 8; ++q) {
            const float4 a = __ldg(&xi4[lane + 32 * q]);
            const float4 b = __ldg(&xn4[lane + 32 * q]);
            s += fabsf(a.x - b.x) + fabsf(a.y - b.y) +
                 fabsf(a.z - b.z) + fabsf(a.w - b.w);
        }
        s = warpReduceSum(s);
        if (lane == 0) s_thr[k] = (s / (float)C) * 0.5f;
    }
    __syncthreads();

    int cnt = 0;
    if (fast) {
#pragma unroll
        for (int k = 0; k < 8; ++k)
            if (k < mc)
                cnt += (fabsf(xic - xnb[k]) < s_thr[k]) ? 1 : 0;
    } else {
        for (int k = 0; k < mc; ++k)
            cnt += (fabsf(xic - __ldg(&x[(size_t)s_nb[k] * C + c])) < s_thr[k]) ? 1 : 0;
    }
    g_W[(size_t)i * C + c] = (float)(cnt * cnt);
}

// ---------------------------------------------------------------------------
// Phase 2 fast path (C == 1024, B % 32 == 0): symmetric upper-triangle tiles,
// packed f32x2 (round-11 form). j-loop unrolled 2x so pass1(j+1) schedules
// under the reduction chains of j. grid (nt*(nt+1)/2, 8); block 256 (8 warps).
// ---------------------------------------------------------------------------
__global__ __launch_bounds__(256) void phase2_sym(
    const float* __restrict__ x,
    const int* __restrict__ targets,
    int B) {
    const int lane = threadIdx.x & 31;
    const int warp = threadIdx.x >> 5;
    const int nt = B >> 5;

    __shared__ ulonglong2 s_wi[8][256];   // 32 KB: packed W row per warp

    // map blockIdx.x -> (tu, tv), tu <= tv, row-major upper triangle
    int t = blockIdx.x;
    int tu = 0;
    while (t >= nt - tu) { t -= (nt - tu); ++tu; }
    const int tv = tu + t;

    const int rowgroup = blockIdx.y >> 1;
    const int jhalf = blockIdx.y & 1;
    const int i = tu * 32 + rowgroup * 8 + warp;
    const int jbase = tv * 32 + jhalf * 16;
    const bool crossTile = (tu != tv);

    const ull SIGN2 = 0x8000000080000000ULL;
    const ull ABS2  = 0x7fffffff7fffffffULL;

    const int ti = __ldg(&targets[i]);
    // row stride: 1024 floats = 256 × 16B
    const ulonglong2* __restrict__ xrow =
        reinterpret_cast<const ulonglong2*>(x) + (size_t)i * 256;
    const ulonglong2* __restrict__ wrow =
        reinterpret_cast<const ulonglong2*>(g_W) + (size_t)i * 256;

    ull xin[16];   // packed (-xi) pairs
#pragma unroll
    for (int k = 0; k < 8; ++k) {
        const ulonglong2 v = __ldg(&xrow[lane + 32 * k]);
        xin[2 * k]     = v.x ^ SIGN2;
        xin[2 * k + 1] = v.y ^ SIGN2;
        s_wi[warp][lane + 32 * k] = __ldg(&wrow[lane + 32 * k]);
    }
    __syncwarp();  // s_wi[warp] used only by this warp

    float modmax = 0.f;
    float idmin = __int_as_float(0x7f800000);

#pragma unroll 2
    for (int jj = 0; jj < 16; ++jj) {
        const int j = jbase + jj;
        const ulonglong2* __restrict__ xj2 =
            reinterpret_cast<const ulonglong2*>(x) + (size_t)j * 256;

        // pass 1 (packed): ad = |xj - xi|, accumulate sum of |.|
        ull ad[16];
        ull sa = 0, sb = 0;
#pragma unroll
        for (int k = 0; k < 8; ++k) {
            const ulonglong2 v = __ldg(&xj2[lane + 32 * k]);
            const ull a = f2_add(xin[2 * k],     v.x) & ABS2;
            const ull b = f2_add(xin[2 * k + 1], v.y) & ABS2;
            ad[2 * k] = a;
            ad[2 * k + 1] = b;
            sa = f2_add(sa, a);
            sb = f2_add(sb, b);
        }
        float sabs = f2_hsum(f2_add(sa, sb));
        sabs = warpReduceSum(sabs);
        const float thr = sabs * (0.5f / 1024.f);
        const uint thrBits = __float_as_uint(thr);   // thr >= 0

        // pass 2 (packed): modsum packed fma; idsum scalar pred-FADD on halves
        const ulonglong2* __restrict__ wj2 =
            reinterpret_cast<const ulonglong2*>(g_W) + (size_t)j * 256;
        ull mod2 = 0;
        float idsum = 0.f;
#pragma unroll
        for (int k = 0; k < 8; ++k) {
            const ulonglong2 wv = __ldg(&wj2[lane + 32 * k]);
            const ulonglong2 wiv = s_wi[warp][lane + 32 * k];
            {
                const ull a = ad[2 * k];
                const ull d2 = f2_mul(a, a);
                mod2 = f2_fma(d2, f2_mul(wiv.x, wv.x), mod2);
                if ((uint)a < thrBits)         idsum += __uint_as_float((uint)d2);
                if ((uint)(a >> 32) < thrBits) idsum += __uint_as_float((uint)(d2 >> 32));
            }
            {
                const ull a = ad[2 * k + 1];
                const ull d2 = f2_mul(a, a);
                mod2 = f2_fma(d2, f2_mul(wiv.y, wv.y), mod2);
                if ((uint)a < thrBits)         idsum += __uint_as_float((uint)d2);
                if ((uint)(a >> 32) < thrBits) idsum += __uint_as_float((uint)(d2 >> 32));
            }
        }
        float modsum = f2_hsum(mod2);
        idsum = warpReduceSum(idsum);
        modsum = warpReduceSum(modsum);

        const float modd = sqrtf(fmaxf(modsum, 1e-12f));
        const float idd = sqrtf(fmaxf(idsum, 1e-12f));
        const int tj = __ldg(&targets[j]);
        const bool diffT = (tj != ti);

        modmax = fmaxf(modmax, modd);
        if (diffT) idmin = fminf(idmin, idd);

        if (lane == 0 && crossTile) {
            atomicMax(&g_modmax_i[j], __float_as_int(modd));
            if (diffT) atomicMin(&g_idmin_i[j], __float_as_int(idd));
        }
    }

    if (lane == 0) {
        atomicMax(&g_modmax_i[i], __float_as_int(modmax));
        atomicMin(&g_idmin_i[i], __float_as_int(idmin));
    }
}

// ---------------------------------------------------------------------------
// Finalize: hinge + mean.
// ---------------------------------------------------------------------------
__global__ void finalize_kernel(float* __restrict__ out, int B) {
    const int tid = threadIdx.x;
    __shared__ float s_red[8];
    float pr = 0.f;
    for (int i = tid; i < B; i += blockDim.x) {
        const float mm = __int_as_float(g_modmax_i[i]);
        const float im = __int_as_float(g_idmin_i[i]);
        pr += fmaxf(mm * 10.f - im, 0.f);   // im=+inf -> -inf -> 0
    }
    pr = blockReduceSum(pr, s_red);
    if (tid == 0) out[0] = pr / (float)B;
}

// ---------------------------------------------------------------------------
// Generic fallback path (any C/B).
// ---------------------------------------------------------------------------
__global__ __launch_bounds__(256) void phase1_kernel(
    const float* __restrict__ x,
    const int* __restrict__ targets,
    const int* __restrict__ subs,
    const int* __restrict__ mcp,
    int B, int C) {
    const int i = blockIdx.x;
    const int tid = threadIdx.x;
    const int lane = tid & 31;
    const int warp = tid >> 5;

    __shared__ int s_t[MAXB];
    __shared__ int s_s[MAXB];
    __shared__ unsigned s_match[8];
    __shared__ unsigned s_valid[8];
    __shared__ int s_nb[16];
    __shared__ float s_thr[16];
    __shared__ int s_mc;

    for (int j = tid; j < B; j += blockDim.x) {
        s_t[j] = targets[j];
        s_s[j] = subs[j];
    }
    if (tid == 0) {
        g_modmax_i[i] = 0;
        g_idmin_i[i] = 0x7f800000;
    }
    __syncthreads();

    {
        const int ti = s_t[i], si = s_s[i];
        const int j = tid;
        const bool valid = (j < B);
        const bool match = valid && (s_t[j] == ti) && (s_s[j] == si);
        const unsigned mm = __ballot_sync(0xffffffffu, match);
        const unsigned vv = __ballot_sync(0xffffffffu, valid);
        if (lane == 0) { s_match[warp] = mm; s_valid[warp] = vv; }
    }
    __syncthreads();

    if (tid == 0) {
        int mc = mcp[0];
        if (mc > 16) mc = 16;
        if (mc < 0) mc = 0;
        int cnt = 0;
        for (int w = 0; w < 8 && cnt < mc; ++w) {
            unsigned m = s_match[w];
            while (m && cnt < mc) { s_nb[cnt++] = w * 32 + (__ffs(m) - 1); m &= m - 1; }
        }
        for (int w = 0; w < 8 && cnt < mc; ++w) {
            unsigned m = s_valid[w] & ~s_match[w];
            while (m && cnt < mc) { s_nb[cnt++] = w * 32 + (__ffs(m) - 1); m &= m - 1; }
        }
        s_mc = cnt;
    }
    __syncthreads();

    const int mc = s_mc;
    const float* __restrict__ xi = x + (size_t)i * C;

    for (int k = warp; k < mc; k += (blockDim.x >> 5)) {
        const float* __restrict__ xn = x + (size_t)s_nb[k] * C;
        float s = 0.f;
        for (int c = lane; c < C; c += 32)
            s += fabsf(xi[c] - xn[c]);
        s = warpReduceSum(s);
        if (lane == 0) s_thr[k] = (s / (float)C) * 0.5f;
    }
    __syncthreads();

    for (int c = tid; c < C; c += blockDim.x) {
        const float xic = xi[c];
        int cnt = 0;
        for (int k = 0; k < mc; ++k)
            cnt += (fabsf(xic - x[(size_t)s_nb[k] * C + c]) < s_thr[k]) ? 1 : 0;
        g_W[(size_t)i * C + c] = (float)(cnt * cnt);
    }
}

__global__ void phase2_generic(const float* __restrict__ x,
                               const int* __restrict__ targets,
                               int B, int C, int jtile) {
    const int i = blockIdx.y;
    const int jt = blockIdx.x;
    const int tid = threadIdx.x;
    __shared__ float s_red[8];
    __shared__ float s_thr;

    const float* xi = x + (size_t)i * C;
    const float* wi = g_W + (size_t)i * C;
    const int ti = targets[i];
    float modmax = 0.f;
    float idmin = __int_as_float(0x7f800000);

    const int j0 = jt * jtile;
    const int j1 = (j0 + jtile < B) ? (j0 + jtile) : B;

    for (int j = j0; j < j1; ++j) {
        const float* xj = x + (size_t)j * C;
        const float* wj = g_W + (size_t)j * C;
        float sabs = 0.f;
        for (int c = tid; c < C; c += blockDim.x)
            sabs += fabsf(xi[c] - xj[c]);
        sabs = blockReduceSum(sabs, s_red);
        if (tid == 0) s_thr = (sabs / (float)C) * 0.5f;
        __syncthreads();
        const float thr = s_thr;

        float idsum = 0.f, modsum = 0.f;
        for (int c = tid; c < C; c += blockDim.x) {
            const float dd = xi[c] - xj[c];
            const float d2 = dd * dd;
            if (fabsf(dd) < thr) idsum += d2;
            modsum += d2 * wi[c] * wj[c];
        }
        idsum = blockReduceSum(idsum, s_red);
        modsum = blockReduceSum(modsum, s_red);
        if (tid == 0) {
            const float modd = sqrtf(fmaxf(modsum, 1e-12f));
            modmax = fmaxf(modmax, modd);
            if (targets[j] != ti) {
                const float idd = sqrtf(fmaxf(idsum, 1e-12f));
                idmin = fminf(idmin, idd);
            }
        }
        __syncthreads();
    }
    if (tid == 0) {
        atomicMax(&g_modmax_i[i], __float_as_int(modmax));
        atomicMin(&g_idmin_i[i], __float_as_int(idmin));
    }
}

// ---------------------------------------------------------------------------
extern "C" void kernel_launch(void* const* d_in, const int* in_sizes, int n_in,
                              void* d_out, int out_size) {
    const float* x = (const float*)d_in[0];
    const int* targets = (const int*)d_in[1];
    const int* subs = (const int*)d_in[2];
    const int* mcp = (const int*)d_in[3];

    const int B = in_sizes[1];             // rows (256)
    const int C = in_sizes[0] / B;         // channels (1024)

    if (C == 1024 && (B & 31) == 0 && B >= 32 && B <= MAXB) {
        p1_big<<<B, 1024>>>(x, targets, subs, mcp, B);
        const int nt = B >> 5;
        dim3 grid(nt * (nt + 1) / 2, 8);
        phase2_sym<<<grid, 256>>>(x, targets, B);
        finalize_kernel<<<1, 256>>>((float*)d_out, B);
    } else {
        phase1_kernel<<<B, 256>>>(x, targets, subs, mcp, B, C);
        const int JT = 8;
        const int jtile = (B + JT - 1) / JT;
        dim3 grid(JT, B);
        phase2_generic<<<grid, 128>>>(x, targets, B, C, jtile);
        finalize_kernel<<<1, 256>>>((float*)d_out, B);
    }
}

// round 16
// speedup vs baseline: 1.3157x; 1.0569x over previous
#include <cuda_runtime.h>

#define MAXB 256
#define MAXC 1024

typedef unsigned long long ull;
typedef unsigned int uint;

// Scratch (static device globals — no allocation allowed)
__device__ __align__(16) float g_W[MAXB * MAXC];  // w[i,c] = m_counts^2
__device__ int   g_modmax_i[MAXB];   // int-encoded non-negative float, atomicMax
__device__ int   g_idmin_i[MAXB];    // int-encoded non-negative float, atomicMin
__device__ unsigned g_sync = 0;      // grid barrier (self-resetting)
__device__ unsigned g_done = 0;      // finalize counter (self-resetting)

// ---- packed f32x2 helpers (Blackwell sm_103a) ----
__device__ __forceinline__ ull f2_add(ull a, ull b) {
    ull r; asm("add.rn.f32x2 %0, %1, %2;" : "=l"(r) : "l"(a), "l"(b)); return r;
}
__device__ __forceinline__ ull f2_mul(ull a, ull b) {
    ull r; asm("mul.rn.f32x2 %0, %1, %2;" : "=l"(r) : "l"(a), "l"(b)); return r;
}
__device__ __forceinline__ ull f2_fma(ull a, ull b, ull c) {
    ull r; asm("fma.rn.f32x2 %0, %1, %2, %3;" : "=l"(r) : "l"(a), "l"(b), "l"(c)); return r;
}
__device__ __forceinline__ float f2_hsum(ull v) {
    return __uint_as_float((uint)v) + __uint_as_float((uint)(v >> 32));
}

__device__ __forceinline__ float warpReduceSum(float v) {
#pragma unroll
    for (int o = 16; o > 0; o >>= 1)
        v += __shfl_xor_sync(0xffffffffu, v, o);
    return v;
}

__device__ __forceinline__ float blockReduceSum(float v, float* sbuf) {
    const int tid = threadIdx.x;
    v = warpReduceSum(v);
    if ((tid & 31) == 0) sbuf[tid >> 5] = v;
    __syncthreads();
    float r = 0.f;
    if (tid == 0) {
        const int nw = (blockDim.x + 31) >> 5;
        for (int w = 0; w < nw; ++w) r += sbuf[w];
    }
    __syncthreads();
    return r;
}

// ---------------------------------------------------------------------------
// FUSED persistent kernel (fast path: C == 1024, B % 32 == 0, B <= 256).
// grid = 288 blocks x 256 threads, __launch_bounds__(256,2) => 2 blocks/SM
// guaranteed => 288 <= 2*148 all resident in wave 1 => spin barrier is safe.
// Phase A: block b < B computes W row b. Grid barrier. Phase B: symmetric
// upper-triangle tile pairs (round-11 packed body). Tail: last block finalizes.
// ---------------------------------------------------------------------------
__global__ __launch_bounds__(256, 2) void fused_all(
    const float* __restrict__ x,
    const int* __restrict__ targets,
    const int* __restrict__ subs,
    const int* __restrict__ mcp,
    int B, float* __restrict__ out) {
    const int tid = threadIdx.x;
    const int lane = tid & 31;
    const int warp = tid >> 5;
    const int C = 1024;

    __shared__ ulonglong2 s_wi[8][256];   // 32 KB (phase B)
    __shared__ unsigned s_match[8];
    __shared__ unsigned s_valid[8];
    __shared__ int s_nb[16];
    __shared__ float s_thr[16];
    __shared__ int s_mc;
    __shared__ float s_red[8];
    __shared__ bool s_last;

    // ================= Phase A: W row bi =================
    const int bi = blockIdx.x;
    if (bi < B) {
        if (tid == 0) {
            g_modmax_i[bi] = 0;
            g_idmin_i[bi] = 0x7f800000;
        }
        const int ti = __ldg(&targets[bi]);
        const int si = __ldg(&subs[bi]);
        {
            const int j = tid;             // 8 warps cover 256 candidates
            const bool valid = (j < B);
            const int tj = valid ? __ldg(&targets[j]) : -1;
            const int sj = valid ? __ldg(&subs[j]) : -1;
            const unsigned mm = __ballot_sync(0xffffffffu, valid && tj == ti && sj == si);
            const unsigned vv = __ballot_sync(0xffffffffu, valid);
            if (lane == 0) { s_match[warp] = mm; s_valid[warp] = vv; }
        }
        __syncthreads();

        if (tid == 0) {
            int mc = __ldg(mcp);
            if (mc > 16) mc = 16;
            if (mc < 0) mc = 0;
            int cnt = 0;
            for (int w = 0; w < 8 && cnt < mc; ++w) {
                unsigned m = s_match[w];
                while (m && cnt < mc) { s_nb[cnt++] = w * 32 + (__ffs(m) - 1); m &= m - 1; }
            }
            for (int w = 0; w < 8 && cnt < mc; ++w) {
                unsigned m = s_valid[w] & ~s_match[w];
                while (m && cnt < mc) { s_nb[cnt++] = w * 32 + (__ffs(m) - 1); m &= m - 1; }
            }
            s_mc = cnt;
        }
        __syncthreads();

        const int mc = s_mc;
        const float4* __restrict__ xi4 =
            reinterpret_cast<const float4*>(x + (size_t)bi * C);

        for (int k = warp; k < mc; k += 8) {
            const float4* __restrict__ xn4 =
                reinterpret_cast<const float4*>(x + (size_t)s_nb[k] * C);
            float s = 0.f;
#pragma unroll
            for (int q = 0; q < 8; ++q) {
                const float4 a = __ldg(&xi4[lane + 32 * q]);
                const float4 b = __ldg(&xn4[lane + 32 * q]);
                s += fabsf(a.x - b.x) + fabsf(a.y - b.y) +
                     fabsf(a.z - b.z) + fabsf(a.w - b.w);
            }
            s = warpReduceSum(s);
            if (lane == 0) s_thr[k] = (s / (float)C) * 0.5f;
        }
        __syncthreads();

        // W: one float4 (4 channels) per thread
        {
            const float4 a = __ldg(&xi4[tid]);
            int c0 = 0, c1 = 0, c2 = 0, c3 = 0;
            for (int k = 0; k < mc; ++k) {
                const float4* __restrict__ xn4 =
                    reinterpret_cast<const float4*>(x + (size_t)s_nb[k] * C);
                const float4 b = __ldg(&xn4[tid]);
                const float th = s_thr[k];
                c0 += (fabsf(a.x - b.x) < th) ? 1 : 0;
                c1 += (fabsf(a.y - b.y) < th) ? 1 : 0;
                c2 += (fabsf(a.z - b.z) < th) ? 1 : 0;
                c3 += (fabsf(a.w - b.w) < th) ? 1 : 0;
            }
            float4 w;
            w.x = (float)(c0 * c0); w.y = (float)(c1 * c1);
            w.z = (float)(c2 * c2); w.w = (float)(c3 * c3);
            reinterpret_cast<float4*>(g_W + (size_t)bi * C)[tid] = w;
        }
    }

    // ================= grid barrier =================
    __syncthreads();
    __threadfence();               // every thread: make its W stores visible
    __syncthreads();
    if (tid == 0) {
        atomicAdd(&g_sync, 1u);
        while (atomicAdd(&g_sync, 0u) < gridDim.x) __nanosleep(128);
        __threadfence();
    }
    __syncthreads();

    // ================= Phase B: pair tiles =================
    const int nt = B >> 5;
    const int nunits = (nt * (nt + 1) / 2) * 8;
    if (blockIdx.x < (unsigned)nunits) {
        int t = blockIdx.x >> 3;
        int tu = 0;
        while (t >= nt - tu) { t -= (nt - tu); ++tu; }
        const int tv = tu + t;
        const int sub = blockIdx.x & 7;
        const int rowgroup = sub >> 1;
        const int jhalf = sub & 1;
        const int i = tu * 32 + rowgroup * 8 + warp;
        const int jbase = tv * 32 + jhalf * 16;
        const bool crossTile = (tu != tv);

        const ull SIGN2 = 0x8000000080000000ULL;
        const ull ABS2  = 0x7fffffff7fffffffULL;

        const int ti = __ldg(&targets[i]);
        const ulonglong2* __restrict__ xrow =
            reinterpret_cast<const ulonglong2*>(x) + (size_t)i * 256;
        const ulonglong2* __restrict__ wrow =
            reinterpret_cast<const ulonglong2*>(g_W) + (size_t)i * 256;

        ull xin[16];   // packed (-xi) pairs
#pragma unroll
        for (int k = 0; k < 8; ++k) {
            const ulonglong2 v = __ldg(&xrow[lane + 32 * k]);
            xin[2 * k]     = v.x ^ SIGN2;
            xin[2 * k + 1] = v.y ^ SIGN2;
            s_wi[warp][lane + 32 * k] = __ldg(&wrow[lane + 32 * k]);
        }
        __syncwarp();  // s_wi[warp] used only by this warp

        float modmax = 0.f;
        float idmin = __int_as_float(0x7f800000);

#pragma unroll 1
        for (int jj = 0; jj < 16; ++jj) {
            const int j = jbase + jj;
            const ulonglong2* __restrict__ xj2 =
                reinterpret_cast<const ulonglong2*>(x) + (size_t)j * 256;

            // pass 1 (packed): ad = |xj - xi|, accumulate sum of |.|
            ull ad[16];
            ull sa = 0, sb = 0;
#pragma unroll
            for (int k = 0; k < 8; ++k) {
                const ulonglong2 v = __ldg(&xj2[lane + 32 * k]);
                const ull a = f2_add(xin[2 * k],     v.x) & ABS2;
                const ull b = f2_add(xin[2 * k + 1], v.y) & ABS2;
                ad[2 * k] = a;
                ad[2 * k + 1] = b;
                sa = f2_add(sa, a);
                sb = f2_add(sb, b);
            }
            float sabs = f2_hsum(f2_add(sa, sb));
            sabs = warpReduceSum(sabs);
            const float thr = sabs * (0.5f / 1024.f);
            const uint thrBits = __float_as_uint(thr);   // thr >= 0

            // pass 2 (packed): modsum packed fma; idsum pred-FADD on halves
            const ulonglong2* __restrict__ wj2 =
                reinterpret_cast<const ulonglong2*>(g_W) + (size_t)j * 256;
            ull mod2 = 0;
            float idsum = 0.f;
#pragma unroll
            for (int k = 0; k < 8; ++k) {
                const ulonglong2 wv = __ldg(&wj2[lane + 32 * k]);
                const ulonglong2 wiv = s_wi[warp][lane + 32 * k];
                {
                    const ull a = ad[2 * k];
                    const ull d2 = f2_mul(a, a);
                    mod2 = f2_fma(d2, f2_mul(wiv.x, wv.x), mod2);
                    if ((uint)a < thrBits)         idsum += __uint_as_float((uint)d2);
                    if ((uint)(a >> 32) < thrBits) idsum += __uint_as_float((uint)(d2 >> 32));
                }
                {
                    const ull a = ad[2 * k + 1];
                    const ull d2 = f2_mul(a, a);
                    mod2 = f2_fma(d2, f2_mul(wiv.y, wv.y), mod2);
                    if ((uint)a < thrBits)         idsum += __uint_as_float((uint)d2);
                    if ((uint)(a >> 32) < thrBits) idsum += __uint_as_float((uint)(d2 >> 32));
                }
            }
            float modsum = f2_hsum(mod2);
            idsum = warpReduceSum(idsum);
            modsum = warpReduceSum(modsum);

            const float modd = sqrtf(fmaxf(modsum, 1e-12f));
            const float idd = sqrtf(fmaxf(idsum, 1e-12f));
            const int tj = __ldg(&targets[j]);
            const bool diffT = (tj != ti);

            modmax = fmaxf(modmax, modd);
            if (diffT) idmin = fminf(idmin, idd);

            if (lane == 0 && crossTile) {
                atomicMax(&g_modmax_i[j], __float_as_int(modd));
                if (diffT) atomicMin(&g_idmin_i[j], __float_as_int(idd));
            }
        }

        if (lane == 0) {
            atomicMax(&g_modmax_i[i], __float_as_int(modmax));
            atomicMin(&g_idmin_i[i], __float_as_int(idmin));
        }
    }

    // ================= tail: last block finalizes =================
    if (lane == 0) __threadfence();   // order this warp's result atomics
    __syncthreads();
    if (tid == 0)
        s_last = (atomicAdd(&g_done, 1u) == gridDim.x - 1u);
    __syncthreads();
    if (s_last) {
        if (tid == 0) {                // reset for next graph replay
            atomicExch(&g_sync, 0u);
            atomicExch(&g_done, 0u);
        }
        float pr = 0.f;
        for (int r = tid; r < B; r += blockDim.x) {
            const float mm = __int_as_float(atomicMax(&g_modmax_i[r], 0));
            const float im = __int_as_float(atomicMin(&g_idmin_i[r], 0x7f800000));
            pr += fmaxf(mm * 10.f - im, 0.f);   // im=+inf -> -inf -> 0
        }
        pr = blockReduceSum(pr, s_red);
        if (tid == 0) out[0] = pr / (float)B;
    }
}

// ---------------------------------------------------------------------------
// Generic fallback path (any C/B).
// ---------------------------------------------------------------------------
__global__ __launch_bounds__(256) void phase1_kernel(
    const float* __restrict__ x,
    const int* __restrict__ targets,
    const int* __restrict__ subs,
    const int* __restrict__ mcp,
    int B, int C) {
    const int i = blockIdx.x;
    const int tid = threadIdx.x;
    const int lane = tid & 31;
    const int warp = tid >> 5;

    __shared__ int s_t[MAXB];
    __shared__ int s_s[MAXB];
    __shared__ unsigned s_match[8];
    __shared__ unsigned s_valid[8];
    __shared__ int s_nb[16];
    __shared__ float s_thr[16];
    __shared__ int s_mc;

    for (int j = tid; j < B; j += blockDim.x) {
        s_t[j] = targets[j];
        s_s[j] = subs[j];
    }
    if (tid == 0) {
        g_modmax_i[i] = 0;
        g_idmin_i[i] = 0x7f800000;
    }
    __syncthreads();

    {
        const int ti = s_t[i], si = s_s[i];
        const int j = tid;
        const bool valid = (j < B);
        const bool match = valid && (s_t[j] == ti) && (s_s[j] == si);
        const unsigned mm = __ballot_sync(0xffffffffu, match);
        const unsigned vv = __ballot_sync(0xffffffffu, valid);
        if (lane == 0) { s_match[warp] = mm; s_valid[warp] = vv; }
    }
    __syncthreads();

    if (tid == 0) {
        int mc = mcp[0];
        if (mc > 16) mc = 16;
        if (mc < 0) mc = 0;
        int cnt = 0;
        for (int w = 0; w < 8 && cnt < mc; ++w) {
            unsigned m = s_match[w];
            while (m && cnt < mc) { s_nb[cnt++] = w * 32 + (__ffs(m) - 1); m &= m - 1; }
        }
        for (int w = 0; w < 8 && cnt < mc; ++w) {
            unsigned m = s_valid[w] & ~s_match[w];
            while (m && cnt < mc) { s_nb[cnt++] = w * 32 + (__ffs(m) - 1); m &= m - 1; }
        }
        s_mc = cnt;
    }
    __syncthreads();

    const int mc = s_mc;
    const float* __restrict__ xi = x + (size_t)i * C;

    for (int k = warp; k < mc; k += (blockDim.x >> 5)) {
        const float* __restrict__ xn = x + (size_t)s_nb[k] * C;
        float s = 0.f;
        for (int c = lane; c < C; c += 32)
            s += fabsf(xi[c] - xn[c]);
        s = warpReduceSum(s);
        if (lane == 0) s_thr[k] = (s / (float)C) * 0.5f;
    }
    __syncthreads();

    for (int c = tid; c < C; c += blockDim.x) {
        const float xic = xi[c];
        int cnt = 0;
        for (int k = 0; k < mc; ++k)
            cnt += (fabsf(xic - x[(size_t)s_nb[k] * C + c]) < s_thr[k]) ? 1 : 0;
        g_W[(size_t)i * C + c] = (float)(cnt * cnt);
    }
}

__global__ void phase2_generic(const float* __restrict__ x,
                               const int* __restrict__ targets,
                               int B, int C, int jtile) {
    const int i = blockIdx.y;
    const int jt = blockIdx.x;
    const int tid = threadIdx.x;
    __shared__ float s_red[8];
    __shared__ float s_thr;

    const float* xi = x + (size_t)i * C;
    const float* wi = g_W + (size_t)i * C;
    const int ti = targets[i];
    float modmax = 0.f;
    float idmin = __int_as_float(0x7f800000);

    const int j0 = jt * jtile;
    const int j1 = (j0 + jtile < B) ? (j0 + jtile) : B;

    for (int j = j0; j < j1; ++j) {
        const float* xj = x + (size_t)j * C;
        const float* wj = g_W + (size_t)j * C;
        float sabs = 0.f;
        for (int c = tid; c < C; c += blockDim.x)
            sabs += fabsf(xi[c] - xj[c]);
        sabs = blockReduceSum(sabs, s_red);
        if (tid == 0) s_thr = (sabs / (float)C) * 0.5f;
        __syncthreads();
        const float thr = s_thr;

        float idsum = 0.f, modsum = 0.f;
        for (int c = tid; c < C; c += blockDim.x) {
            const float dd = xi[c] - xj[c];
            const float d2 = dd * dd;
            if (fabsf(dd) < thr) idsum += d2;
            modsum += d2 * wi[c] * wj[c];
        }
        idsum = blockReduceSum(idsum, s_red);
        modsum = blockReduceSum(modsum, s_red);
        if (tid == 0) {
            const float modd = sqrtf(fmaxf(modsum, 1e-12f));
            modmax = fmaxf(modmax, modd);
            if (targets[j] != ti) {
                const float idd = sqrtf(fmaxf(idsum, 1e-12f));
                idmin = fminf(idmin, idd);
            }
        }
        __syncthreads();
    }
    if (tid == 0) {
        atomicMax(&g_modmax_i[i], __float_as_int(modmax));
        atomicMin(&g_idmin_i[i], __float_as_int(idmin));
    }
}

__global__ void finalize_kernel(float* __restrict__ out, int B) {
    const int tid = threadIdx.x;
    __shared__ float s_red[8];
    float pr = 0.f;
    for (int i = tid; i < B; i += blockDim.x) {
        const float mm = __int_as_float(g_modmax_i[i]);
        const float im = __int_as_float(g_idmin_i[i]);
        pr += fmaxf(mm * 10.f - im, 0.f);
    }
    pr = blockReduceSum(pr, s_red);
    if (tid == 0) out[0] = pr / (float)B;
}

// ---------------------------------------------------------------------------
extern "C" void kernel_launch(void* const* d_in, const int* in_sizes, int n_in,
                              void* d_out, int out_size) {
    const float* x = (const float*)d_in[0];
    const int* targets = (const int*)d_in[1];
    const int* subs = (const int*)d_in[2];
    const int* mcp = (const int*)d_in[3];

    const int B = in_sizes[1];             // rows (256)
    const int C = in_sizes[0] / B;         // channels (1024)

    if (C == 1024 && (B & 31) == 0 && B >= 32 && B <= MAXB) {
        // Grid 288 <= 2 blocks/SM * 148 SMs — whole grid resident (barrier-safe)
        fused_all<<<288, 256>>>(x, targets, subs, mcp, B, (float*)d_out);
    } else {
        phase1_kernel<<<B, 256>>>(x, targets, subs, mcp, B, C);
        const int JT = 8;
        const int jtile = (B + JT - 1) / JT;
        dim3 grid(JT, B);
        phase2_generic<<<grid, 128>>>(x, targets, B, C, jtile);
        finalize_kernel<<<1, 256>>>((float*)d_out, B);
    }
}